// round 10
// baseline (speedup 1.0000x reference)
#include <cuda_runtime.h>
#include <cuda_bf16.h>

// y = Re(FFT_2048(x_row)); out = LayerNorm(y)*gamma + beta.  16384 rows, C=2048.
// Four-step FFT: 1024 = 32x32, one warp/row, 32 complex elems/thread.
// Register FFT-32 (radix-2 DIF, const twiddles), one padded smem transpose,
// conjugate unpack via linear smem publish, LN warp reduce.
// R8: register diet -> 6 CTAs/SM. Two-chain step-2 twiddles (low live regs),
// store loop unroll capped, launch_bounds(128,6).

#define C 2048
#define H 1024
#define RPC 4
#define PITCH 33
#define PI_F 3.14159265358979323846f
#define RS2 0.70710678118654752f

__device__ __forceinline__ float2 cmul(float2 a, float2 b) {
    return make_float2(fmaf(a.x, b.x, -a.y * b.y), fmaf(a.x, b.y, a.y * b.x));
}
__device__ __forceinline__ float2 csq(float2 a) {
    return make_float2(fmaf(a.x, a.x, -a.y * a.y), 2.0f * a.x * a.y);
}
__device__ __forceinline__ float2 cadd(float2 a, float2 b) { return make_float2(a.x + b.x, a.y + b.y); }
__device__ __forceinline__ float2 csub(float2 a, float2 b) { return make_float2(a.x - b.x, a.y - b.y); }

__device__ __forceinline__ int br5(int x) {
    return ((x & 1) << 4) | ((x & 2) << 2) | (x & 4) | ((x & 8) >> 2) | ((x & 16) >> 4);
}

__device__ __forceinline__ float2 w32c(int e) {
    const float CO[16] = {1.f, 0.98078528f, 0.92387953f, 0.83146961f, 0.70710678f,
                          0.55557023f, 0.38268343f, 0.19509032f, 0.f, -0.19509032f,
                          -0.38268343f, -0.55557023f, -0.70710678f, -0.83146961f,
                          -0.92387953f, -0.98078528f};
    const float SI[16] = {0.f, 0.19509032f, 0.38268343f, 0.55557023f, 0.70710678f,
                          0.83146961f, 0.92387953f, 0.98078528f, 1.f, 0.98078528f,
                          0.92387953f, 0.83146961f, 0.70710678f, 0.55557023f,
                          0.38268343f, 0.19509032f};
    return make_float2(CO[e], -SI[e]);
}

template <int M>
__device__ __forceinline__ void fft32_stage(float2 v[32]) {
#pragma unroll
    for (int b = 0; b < 32; b += 2 * M)
#pragma unroll
        for (int i = 0; i < M; i++) {
            float2 u = v[b + i], t = v[b + i + M];
            v[b + i] = cadd(u, t);
            float2 d = csub(u, t);
            const int e = i * (16 / M);
            if (e == 0)      v[b + i + M] = d;
            else if (e == 8) v[b + i + M] = make_float2(d.y, -d.x);  // *(-i)
            else             v[b + i + M] = cmul(d, w32c(e));
        }
}
__device__ __forceinline__ void fft32(float2 v[32]) {
    fft32_stage<16>(v); fft32_stage<8>(v); fft32_stage<4>(v);
    fft32_stage<2>(v);  fft32_stage<1>(v);
}

__global__ void __launch_bounds__(128, 6)
fourier_ln_kernel(const float* __restrict__ x,
                  const float* __restrict__ gamma,
                  const float* __restrict__ beta,
                  float* __restrict__ out) {
    __shared__ __align__(16) float2 xch[RPC][32 * PITCH];

    const int lane = threadIdx.x & 31;
    const int warp = threadIdx.x >> 5;
    const size_t row = (size_t)blockIdx.x * RPC + warp;
    const float2* xr = reinterpret_cast<const float2*>(x) + row * H;

    // step 1: coalesced load, FFT-32 over b
    float2 g[32];
#pragma unroll
    for (int b = 0; b < 32; b++) g[b] = xr[lane + 32 * b];
    fft32(g);                    // g[br5(c)] = G_a[c]

    // step 2: G_a[c] *= W_1024^{a*c}; two chains (odd/even c), low live regs
    {
        float sb, cb;
        __sincosf(-(float)lane * (PI_F / 512.0f), &sb, &cb);
        float2 p1 = make_float2(cb, sb);     // W_1024^a
        float2 p2 = csq(p1);                 // W_1024^{2a}
        float2 wo = p1;                      // odd chain:  c = 1,3,...,31
        float2 we = p2;                      // even chain: c = 2,4,...,30
#pragma unroll
        for (int c = 1; c < 16; c++) {
            g[br5(2 * c - 1)] = cmul(g[br5(2 * c - 1)], wo);
            g[br5(2 * c)]     = cmul(g[br5(2 * c)],     we);
            wo = cmul(wo, p2);
            we = cmul(we, p2);
        }
        g[br5(31)] = cmul(g[br5(31)], wo);
    }

    // step 3: 32x32 transpose through padded smem
    float2* sh = &xch[warp][0];
#pragma unroll
    for (int c = 0; c < 32; c++) sh[lane * PITCH + c] = g[br5(c)];
    __syncwarp();
#pragma unroll
    for (int a = 0; a < 32; a++) g[a] = sh[a * PITCH + lane];

    // step 4: FFT-32 over a.  g[br5(d)] = Z[lane + 32*d]
    fft32(g);
    const float re1024 = g[0].x - g[0].y;      // lane 0: ReX[1024]

    // publish Z linearly for conjugate-partner reads (conflict-free)
    __syncwarp();
#pragma unroll
    for (int d = 0; d < 32; d++) sh[lane + 32 * d] = g[br5(d)];
    __syncwarp();

    // unpack ReX[k] + LN partials; one depth-8 chain drives 4 groups
    float s = 0.f, ss = 0.f;
    {
        float su, cu;
        __sincosf(-(float)lane * (PI_F / 1024.0f), &su, &cu);
        float2 wu = make_float2(cu, su);                        // e^{-i pi k/1024}, k=lane
        const float2 ustep = make_float2(0.99518472667f, -0.09801714033f); // e^{-i pi/32}
        const float2 c8  = make_float2(RS2, -RS2);              // e^{-i pi/4}
        const float2 c24 = make_float2(-RS2, -RS2);             // e^{-i 3pi/4}
#pragma unroll
        for (int dd = 0; dd < 8; dd++) {
#pragma unroll
            for (int q = 0; q < 4; q++) {
                const int d = q * 8 + dd;
                float2 w;
                if (q == 0)      w = wu;
                else if (q == 1) w = cmul(wu, c8);
                else if (q == 2) w = make_float2(wu.y, -wu.x);  // wu * (-i)
                else             w = cmul(wu, c24);
                int k = lane + 32 * d;
                float2 z = g[br5(d)];
                float2 p = sh[(H - k) & (H - 1)];
                float red = 0.5f * ((z.x + p.x) +
                            fmaf(w.x, z.y + p.y, w.y * (z.x - p.x)));
                g[br5(d)].x = red;
                s  += 2.0f * red;
                ss = fmaf(2.0f * red, red, ss);
            }
            if (dd < 7) wu = cmul(wu, ustep);
        }
    }
    if (lane == 0) {
        float re0 = g[br5(0)].x;
        s  += re1024 - re0;
        ss += fmaf(re1024, re1024, -re0 * re0);
    }
#pragma unroll
    for (int o = 16; o > 0; o >>= 1) {
        s  += __shfl_xor_sync(0xFFFFFFFFu, s, o);
        ss += __shfl_xor_sync(0xFFFFFFFFu, ss, o);
    }
    const float mu = s * (1.0f / C);
    const float rstd = rsqrtf(ss * (1.0f / C) - mu * mu + 1e-5f);

    // normalize + affine + mirrored stores (unroll capped: reg pressure)
    float* orow = out + row * C;
#pragma unroll 4
    for (int d = 0; d < 32; d++) {
        int k = lane + 32 * d;
        float vv = (g[br5(d)].x - mu) * rstd;
        orow[k] = fmaf(vv, __ldg(&gamma[k]), __ldg(&beta[k]));
        if (k != 0) {
            int km = C - k;
            orow[km] = fmaf(vv, __ldg(&gamma[km]), __ldg(&beta[km]));
        }
    }
    if (lane == 0) {
        float vv = (re1024 - mu) * rstd;
        orow[H] = fmaf(vv, __ldg(&gamma[H]), __ldg(&beta[H]));
    }
}

extern "C" void kernel_launch(void* const* d_in, const int* in_sizes, int n_in,
                              void* d_out, int out_size) {
    const float* x     = (const float*)d_in[0];
    const float* gamma = (const float*)d_in[1];
    const float* beta  = (const float*)d_in[2];
    float* out = (float*)d_out;
    int rows = in_sizes[0] / C;            // 16384
    fourier_ln_kernel<<<rows / RPC, 32 * RPC>>>(x, gamma, beta, out);
}

// round 13
// speedup vs baseline: 1.8119x; 1.8119x over previous
#include <cuda_runtime.h>
#include <cuda_bf16.h>

// y = Re(FFT_2048(x_row)); out = LayerNorm(y)*gamma + beta.  16384 rows, C=2048.
// Four-step FFT 1024 = 32x32, TWO warps per row, 16 complex elems/thread.
// Each FFT-32 = cross-half radix-2 DIF (shfl.xor 16; odd-branch twiddle
// W_32^j = COMPILE-TIME constant, j = register index) + register FFT-16.
// One padded smem transpose + linear publish for conjugate unpack. LN reduce
// across the 2 row-warps via smem. All loops fully unrolled, indices static.

#define C 2048
#define H 1024
#define PI_F 3.14159265358979323846f

__device__ __forceinline__ float2 cmul(float2 a, float2 b) {
    return make_float2(fmaf(a.x, b.x, -a.y * b.y), fmaf(a.x, b.y, a.y * b.x));
}

__device__ __forceinline__ int br4(int x) {
    return ((x & 1) << 3) | ((x & 2) << 1) | ((x & 4) >> 1) | ((x & 8) >> 3);
}

// W_32^e = exp(-2*pi*i*e/32), e in [0,16). Compile-time folded.
__device__ __forceinline__ float2 w32c(int e) {
    const float CO[16] = {1.f, 0.98078528f, 0.92387953f, 0.83146961f, 0.70710678f,
                          0.55557023f, 0.38268343f, 0.19509032f, 0.f, -0.19509032f,
                          -0.38268343f, -0.55557023f, -0.70710678f, -0.83146961f,
                          -0.92387953f, -0.98078528f};
    const float SI[16] = {0.f, 0.19509032f, 0.38268343f, 0.55557023f, 0.70710678f,
                          0.83146961f, 0.92387953f, 0.98078528f, 1.f, 0.98078528f,
                          0.92387953f, 0.83146961f, 0.70710678f, 0.55557023f,
                          0.38268343f, 0.19509032f};
    return make_float2(CO[e], -SI[e]);
}

// W_16^e = exp(-2*pi*i*e/16), e in [0,8). Compile-time folded.
__device__ __forceinline__ float2 w16c(int e) {
    const float CO[8] = {1.f, 0.92387953f, 0.70710678f, 0.38268343f,
                         0.f, -0.38268343f, -0.70710678f, -0.92387953f};
    const float SI[8] = {0.f, 0.38268343f, 0.70710678f, 0.92387953f,
                         1.f, 0.92387953f, 0.70710678f, 0.38268343f};
    return make_float2(CO[e], -SI[e]);
}

template <int M>
__device__ __forceinline__ void fft16_stage(float2 v[16]) {
#pragma unroll
    for (int b = 0; b < 16; b += 2 * M)
#pragma unroll
        for (int i = 0; i < M; i++) {
            float2 u = v[b + i], t = v[b + i + M];
            v[b + i] = make_float2(u.x + t.x, u.y + t.y);
            float2 d = make_float2(u.x - t.x, u.y - t.y);
            const int e = i * (8 / M);
            if (e == 0)      v[b + i + M] = d;
            else if (e == 4) v[b + i + M] = make_float2(d.y, -d.x);  // *(-i)
            else             v[b + i + M] = cmul(d, w16c(e));
        }
}
// Radix-2 DIF: natural in, out v[r] = X[br4(r)].
__device__ __forceinline__ void fft16(float2 v[16]) {
    fft16_stage<8>(v); fft16_stage<4>(v); fft16_stage<2>(v); fft16_stage<1>(v);
}

// Cross-half radix-2 DIF step over the 32-long dimension split as lane-bit-4.
// h=0 threads end with s[j] = z[j]+z[j+16]; h=1 with (z[j]-z[j+16])*W_32^j.
__device__ __forceinline__ void crosshalf(float2 v[16], int h) {
#pragma unroll
    for (int j = 0; j < 16; j++) {
        float ox = __shfl_xor_sync(0xFFFFFFFFu, v[j].x, 16);
        float oy = __shfl_xor_sync(0xFFFFFFFFu, v[j].y, 16);
        float2 su = make_float2(v[j].x + ox, v[j].y + oy);
        float2 df = make_float2(ox - v[j].x, oy - v[j].y);   // z[j]-z[j+16] on h=1
        float2 dfw = (j == 0) ? df
                   : (j == 8) ? make_float2(df.y, -df.x)     // *(-i)
                              : cmul(df, w32c(j));
        v[j] = h ? dfw : su;
    }
}

__global__ void __launch_bounds__(128, 6)
fourier_ln_kernel(const float* __restrict__ x,
                  const float* __restrict__ gamma,
                  const float* __restrict__ beta,
                  float* __restrict__ out) {
    __shared__ __align__(16) float2 xch[2][32 * 33];   // per-row transpose/publish
    __shared__ float red[2][2][2];

    const int l = threadIdx.x & 31;
    const int w = threadIdx.x >> 5;
    const int rowi = w >> 1;          // row within CTA
    const int p = w & 1;              // warp within row-pair
    const int a = (l & 15) + 16 * p;  // column index (also c' for 2nd FFT)
    const int h = l >> 4;             // half: 0 = even outputs, 1 = odd outputs

    const size_t row = (size_t)blockIdx.x * 2 + rowi;
    const float2* xr = reinterpret_cast<const float2*>(x) + row * H;
    float2* sh = &xch[rowi][0];

    // ---- step 1: load (coalesced), cross-half radix-2, FFT-16 over b ----
    float2 v[16];
#pragma unroll
    for (int j = 0; j < 16; j++) v[j] = xr[a + 32 * (16 * h + j)];
    crosshalf(v, h);
    fft16(v);          // v[r] = G_a[c], c = 2*br4(r) + h

    // ---- step 2: twiddle W_1024^{a*c} = W_1024^{a*h} * (W_512^a)^m, m=br4(r) ----
    {
        float sb, cb;
        __sincosf(-(float)a * (PI_F / 256.0f), &sb, &cb);    // W_512^a
        float2 B = make_float2(cb, sb);
        float2 w2;
        if (h) { float s1, c1; __sincosf(-(float)a * (PI_F / 512.0f), &s1, &c1);
                 w2 = make_float2(c1, s1); }                 // W_1024^a
        else   w2 = make_float2(1.f, 0.f);
#pragma unroll
        for (int m = 0; m < 16; m++) {
            v[br4(m)] = cmul(v[br4(m)], w2);
            w2 = cmul(w2, B);
        }
    }

    // ---- step 3: 32x32 transpose through padded smem ----
#pragma unroll
    for (int r = 0; r < 16; r++) {
        int c = 2 * br4(r) + h;
        sh[c * 33 + a] = v[r];
    }
    __syncthreads();
#pragma unroll
    for (int i = 0; i < 16; i++) v[i] = sh[a * 33 + i + 16 * h];  // G_{i+16h}[c'=a]
    __syncthreads();

    // ---- step 4: cross-half radix-2 over G-row index, FFT-16 ----
    crosshalf(v, h);
    fft16(v);          // v[r] = Z[a + 32*(2*br4(r)+h)]

    const float re1024 = v[0].x - v[0].y;     // valid on (p==0, l==0): Z[0]

    // ---- publish Z linearly for conjugate reads ----
#pragma unroll
    for (int r = 0; r < 16; r++) {
        int k = a + 32 * (2 * br4(r) + h);
        sh[k] = v[r];
    }
    __syncthreads();

    // ---- unpack ReX[k] + LN partials ----
    float s = 0.f, ss = 0.f;
    {
        float su, cu;
        __sincosf(-(float)a * (PI_F / 1024.0f), &su, &cu);
        float2 wu = make_float2(cu, su);                       // e^{-i pi a/1024}
        if (h) wu = cmul(wu, make_float2(0.99518473f, -0.09801714f)); // * e^{-i pi/32}
        const float2 M2 = make_float2(0.98078528f, -0.19509032f);     // e^{-i pi/16}
#pragma unroll
        for (int m = 0; m < 16; m++) {
            const int r = br4(m);
            int k = a + 32 * (2 * m + h);
            float2 z = v[r];
            float2 pt = sh[(H - k) & (H - 1)];
            float re = 0.5f * ((z.x + pt.x) +
                       fmaf(wu.x, z.y + pt.y, wu.y * (z.x - pt.x)));
            v[r].x = re;
            s  += 2.0f * re;
            ss  = fmaf(2.0f * re, re, ss);
            wu = cmul(wu, M2);
        }
    }
    if (p == 0 && l == 0) {            // k=0 and k=1024 count once each
        float re0 = v[0].x;
        s  += re1024 - re0;
        ss += fmaf(re1024, re1024, -re0 * re0);
    }
#pragma unroll
    for (int o = 16; o > 0; o >>= 1) {
        s  += __shfl_xor_sync(0xFFFFFFFFu, s, o);
        ss += __shfl_xor_sync(0xFFFFFFFFu, ss, o);
    }
    if (l == 0) { red[rowi][p][0] = s; red[rowi][p][1] = ss; }
    __syncthreads();
    const float S  = red[rowi][0][0] + red[rowi][1][0];
    const float SS = red[rowi][0][1] + red[rowi][1][1];
    const float mu = S * (1.0f / C);
    const float rstd = rsqrtf(SS * (1.0f / C) - mu * mu + 1e-5f);

    // ---- normalize + affine + mirrored stores ----
    float* orow = out + row * C;
#pragma unroll
    for (int m = 0; m < 16; m++) {
        const int r = br4(m);
        int k = a + 32 * (2 * m + h);
        float vv = (v[r].x - mu) * rstd;
        orow[k] = fmaf(vv, __ldg(&gamma[k]), __ldg(&beta[k]));
        if (k != 0) {
            int km = C - k;
            orow[km] = fmaf(vv, __ldg(&gamma[km]), __ldg(&beta[km]));
        }
    }
    if (p == 0 && l == 0) {
        float vv = (re1024 - mu) * rstd;
        orow[H] = fmaf(vv, __ldg(&gamma[H]), __ldg(&beta[H]));
    }
}

extern "C" void kernel_launch(void* const* d_in, const int* in_sizes, int n_in,
                              void* d_out, int out_size) {
    const float* x     = (const float*)d_in[0];
    const float* gamma = (const float*)d_in[1];
    const float* beta  = (const float*)d_in[2];
    float* out = (float*)d_out;
    int rows = in_sizes[0] / C;            // 16384
    fourier_ln_kernel<<<rows / 2, 128>>>(x, gamma, beta, out);
}

// round 14
// speedup vs baseline: 1.8155x; 1.0020x over previous
#include <cuda_runtime.h>
#include <cuda_bf16.h>

// y = Re(FFT_2048(x_row)); out = LayerNorm(y)*gamma + beta.  16384 rows, C=2048.
// Four-step FFT: 1024 = 32x32, one warp/row, 32 complex elems/thread.
// Register FFT-32 (radix-2 DIF, const twiddles), one padded smem transpose,
// conjugate unpack via linear smem publish, LN warp reduce.
// R14 = R6 + two-chain step-2 twiddles (low live regs) + launch_bounds(128,6).
// All loops fully unrolled; every g[] index is compile-time static.

#define C 2048
#define H 1024
#define RPC 4
#define PITCH 33
#define PI_F 3.14159265358979323846f
#define RS2 0.70710678118654752f

__device__ __forceinline__ float2 cmul(float2 a, float2 b) {
    return make_float2(fmaf(a.x, b.x, -a.y * b.y), fmaf(a.x, b.y, a.y * b.x));
}
__device__ __forceinline__ float2 csq(float2 a) {
    return make_float2(fmaf(a.x, a.x, -a.y * a.y), 2.0f * a.x * a.y);
}
__device__ __forceinline__ float2 cadd(float2 a, float2 b) { return make_float2(a.x + b.x, a.y + b.y); }
__device__ __forceinline__ float2 csub(float2 a, float2 b) { return make_float2(a.x - b.x, a.y - b.y); }

__device__ __forceinline__ int br5(int x) {
    return ((x & 1) << 4) | ((x & 2) << 2) | (x & 4) | ((x & 8) >> 2) | ((x & 16) >> 4);
}

__device__ __forceinline__ float2 w32c(int e) {
    const float CO[16] = {1.f, 0.98078528f, 0.92387953f, 0.83146961f, 0.70710678f,
                          0.55557023f, 0.38268343f, 0.19509032f, 0.f, -0.19509032f,
                          -0.38268343f, -0.55557023f, -0.70710678f, -0.83146961f,
                          -0.92387953f, -0.98078528f};
    const float SI[16] = {0.f, 0.19509032f, 0.38268343f, 0.55557023f, 0.70710678f,
                          0.83146961f, 0.92387953f, 0.98078528f, 1.f, 0.98078528f,
                          0.92387953f, 0.83146961f, 0.70710678f, 0.55557023f,
                          0.38268343f, 0.19509032f};
    return make_float2(CO[e], -SI[e]);
}

template <int M>
__device__ __forceinline__ void fft32_stage(float2 v[32]) {
#pragma unroll
    for (int b = 0; b < 32; b += 2 * M)
#pragma unroll
        for (int i = 0; i < M; i++) {
            float2 u = v[b + i], t = v[b + i + M];
            v[b + i] = cadd(u, t);
            float2 d = csub(u, t);
            const int e = i * (16 / M);
            if (e == 0)      v[b + i + M] = d;
            else if (e == 8) v[b + i + M] = make_float2(d.y, -d.x);  // *(-i)
            else             v[b + i + M] = cmul(d, w32c(e));
        }
}
__device__ __forceinline__ void fft32(float2 v[32]) {
    fft32_stage<16>(v); fft32_stage<8>(v); fft32_stage<4>(v);
    fft32_stage<2>(v);  fft32_stage<1>(v);
}

__global__ void __launch_bounds__(128, 6)
fourier_ln_kernel(const float* __restrict__ x,
                  const float* __restrict__ gamma,
                  const float* __restrict__ beta,
                  float* __restrict__ out) {
    __shared__ __align__(16) float2 xch[RPC][32 * PITCH];

    const int lane = threadIdx.x & 31;
    const int warp = threadIdx.x >> 5;
    const size_t row = (size_t)blockIdx.x * RPC + warp;
    const float2* xr = reinterpret_cast<const float2*>(x) + row * H;

    // step 1: coalesced load, FFT-32 over b
    float2 g[32];
#pragma unroll
    for (int b = 0; b < 32; b++) g[b] = xr[lane + 32 * b];
    fft32(g);                    // g[br5(c)] = G_a[c]

    // step 2: G_a[c] *= W_1024^{a*c}; two chains (odd/even c), few live regs
    {
        float sb, cb;
        __sincosf(-(float)lane * (PI_F / 512.0f), &sb, &cb);
        float2 p1 = make_float2(cb, sb);     // W_1024^a
        float2 p2 = csq(p1);                 // W_1024^{2a}
        float2 wo = p1;                      // odd chain:  c = 1,3,...,31
        float2 we = p2;                      // even chain: c = 2,4,...,30
#pragma unroll
        for (int c = 1; c < 16; c++) {
            g[br5(2 * c - 1)] = cmul(g[br5(2 * c - 1)], wo);
            g[br5(2 * c)]     = cmul(g[br5(2 * c)],     we);
            wo = cmul(wo, p2);
            we = cmul(we, p2);
        }
        g[br5(31)] = cmul(g[br5(31)], wo);
    }

    // step 3: 32x32 transpose through padded smem
    float2* sh = &xch[warp][0];
#pragma unroll
    for (int c = 0; c < 32; c++) sh[lane * PITCH + c] = g[br5(c)];
    __syncwarp();
#pragma unroll
    for (int a = 0; a < 32; a++) g[a] = sh[a * PITCH + lane];

    // step 4: FFT-32 over a.  g[br5(d)] = Z[lane + 32*d]
    fft32(g);
    const float re1024 = g[0].x - g[0].y;      // lane 0: ReX[1024]

    // publish Z linearly for conjugate-partner reads (conflict-free)
    __syncwarp();
#pragma unroll
    for (int d = 0; d < 32; d++) sh[lane + 32 * d] = g[br5(d)];
    __syncwarp();

    // unpack ReX[k] + LN partials; one depth-8 chain drives 4 groups
    float s = 0.f, ss = 0.f;
    {
        float su, cu;
        __sincosf(-(float)lane * (PI_F / 1024.0f), &su, &cu);
        float2 wu = make_float2(cu, su);                        // e^{-i pi k/1024}, k=lane
        const float2 ustep = make_float2(0.99518472667f, -0.09801714033f); // e^{-i pi/32}
        const float2 c8  = make_float2(RS2, -RS2);              // e^{-i pi/4}
        const float2 c24 = make_float2(-RS2, -RS2);             // e^{-i 3pi/4}
#pragma unroll
        for (int dd = 0; dd < 8; dd++) {
#pragma unroll
            for (int q = 0; q < 4; q++) {
                const int d = q * 8 + dd;
                float2 w;
                if (q == 0)      w = wu;
                else if (q == 1) w = cmul(wu, c8);
                else if (q == 2) w = make_float2(wu.y, -wu.x);  // wu * (-i)
                else             w = cmul(wu, c24);
                int k = lane + 32 * d;
                float2 z = g[br5(d)];
                float2 p = sh[(H - k) & (H - 1)];
                float red = 0.5f * ((z.x + p.x) +
                            fmaf(w.x, z.y + p.y, w.y * (z.x - p.x)));
                g[br5(d)].x = red;
                s  += 2.0f * red;
                ss = fmaf(2.0f * red, red, ss);
            }
            if (dd < 7) wu = cmul(wu, ustep);
        }
    }
    if (lane == 0) {
        float re0 = g[br5(0)].x;
        s  += re1024 - re0;
        ss += fmaf(re1024, re1024, -re0 * re0);
    }
#pragma unroll
    for (int o = 16; o > 0; o >>= 1) {
        s  += __shfl_xor_sync(0xFFFFFFFFu, s, o);
        ss += __shfl_xor_sync(0xFFFFFFFFu, ss, o);
    }
    const float mu = s * (1.0f / C);
    const float rstd = rsqrtf(ss * (1.0f / C) - mu * mu + 1e-5f);

    // normalize + affine + mirrored stores (FULLY unrolled; static indices)
    float* orow = out + row * C;
#pragma unroll
    for (int d = 0; d < 32; d++) {
        int k = lane + 32 * d;
        float vv = (g[br5(d)].x - mu) * rstd;
        orow[k] = fmaf(vv, __ldg(&gamma[k]), __ldg(&beta[k]));
        if (k != 0) {
            int km = C - k;
            orow[km] = fmaf(vv, __ldg(&gamma[km]), __ldg(&beta[km]));
        }
    }
    if (lane == 0) {
        float vv = (re1024 - mu) * rstd;
        orow[H] = fmaf(vv, __ldg(&gamma[H]), __ldg(&beta[H]));
    }
}

extern "C" void kernel_launch(void* const* d_in, const int* in_sizes, int n_in,
                              void* d_out, int out_size) {
    const float* x     = (const float*)d_in[0];
    const float* gamma = (const float*)d_in[1];
    const float* beta  = (const float*)d_in[2];
    float* out = (float*)d_out;
    int rows = in_sizes[0] / C;            // 16384
    fourier_ln_kernel<<<rows / RPC, 32 * RPC>>>(x, gamma, beta, out);
}

// round 16
// speedup vs baseline: 2.1001x; 1.1567x over previous
#include <cuda_runtime.h>
#include <cuda_bf16.h>

// y = Re(FFT_2048(x_row)); out = LayerNorm(y)*gamma + beta.  16384 rows, C=2048.
// Four-step FFT: 1024 = 32x32, one warp/row, 32 complex elems/thread.
// Register FFT-32 (radix-2 DIF, const twiddles), one padded smem transpose,
// conjugate unpack via linear smem publish, LN warp reduce.
// R16 = R6 core (ladder twiddles, occ 5) + float4 smem-staged epilogue:
// re -> smem (direct+mirror), then LDS.128/LDG.128/STG.128 uniform tail.
// (Identical to R15 submission; R15 bench was an infra failure.)

#define C 2048
#define H 1024
#define RPC 4
#define PITCH 33
#define PI_F 3.14159265358979323846f
#define RS2 0.70710678118654752f

__device__ __forceinline__ float2 cmul(float2 a, float2 b) {
    return make_float2(fmaf(a.x, b.x, -a.y * b.y), fmaf(a.x, b.y, a.y * b.x));
}
__device__ __forceinline__ float2 csq(float2 a) {
    return make_float2(fmaf(a.x, a.x, -a.y * a.y), 2.0f * a.x * a.y);
}
__device__ __forceinline__ float2 cadd(float2 a, float2 b) { return make_float2(a.x + b.x, a.y + b.y); }
__device__ __forceinline__ float2 csub(float2 a, float2 b) { return make_float2(a.x - b.x, a.y - b.y); }

__device__ __forceinline__ int br5(int x) {
    return ((x & 1) << 4) | ((x & 2) << 2) | (x & 4) | ((x & 8) >> 2) | ((x & 16) >> 4);
}

__device__ __forceinline__ float2 w32c(int e) {
    const float CO[16] = {1.f, 0.98078528f, 0.92387953f, 0.83146961f, 0.70710678f,
                          0.55557023f, 0.38268343f, 0.19509032f, 0.f, -0.19509032f,
                          -0.38268343f, -0.55557023f, -0.70710678f, -0.83146961f,
                          -0.92387953f, -0.98078528f};
    const float SI[16] = {0.f, 0.19509032f, 0.38268343f, 0.55557023f, 0.70710678f,
                          0.83146961f, 0.92387953f, 0.98078528f, 1.f, 0.98078528f,
                          0.92387953f, 0.83146961f, 0.70710678f, 0.55557023f,
                          0.38268343f, 0.19509032f};
    return make_float2(CO[e], -SI[e]);
}

template <int M>
__device__ __forceinline__ void fft32_stage(float2 v[32]) {
#pragma unroll
    for (int b = 0; b < 32; b += 2 * M)
#pragma unroll
        for (int i = 0; i < M; i++) {
            float2 u = v[b + i], t = v[b + i + M];
            v[b + i] = cadd(u, t);
            float2 d = csub(u, t);
            const int e = i * (16 / M);
            if (e == 0)      v[b + i + M] = d;
            else if (e == 8) v[b + i + M] = make_float2(d.y, -d.x);  // *(-i)
            else             v[b + i + M] = cmul(d, w32c(e));
        }
}
__device__ __forceinline__ void fft32(float2 v[32]) {
    fft32_stage<16>(v); fft32_stage<8>(v); fft32_stage<4>(v);
    fft32_stage<2>(v);  fft32_stage<1>(v);
}

__global__ void __launch_bounds__(128, 5)
fourier_ln_kernel(const float* __restrict__ x,
                  const float* __restrict__ gamma,
                  const float* __restrict__ beta,
                  float* __restrict__ out) {
    __shared__ __align__(16) float2 xch[RPC][32 * PITCH];   // 1056 float2/warp

    const int lane = threadIdx.x & 31;
    const int warp = threadIdx.x >> 5;
    const size_t row = (size_t)blockIdx.x * RPC + warp;
    const float2* xr = reinterpret_cast<const float2*>(x) + row * H;

    // step 1: coalesced load, FFT-32 over b
    float2 g[32];
#pragma unroll
    for (int b = 0; b < 32; b++) g[b] = xr[lane + 32 * b];
    fft32(g);                    // g[br5(c)] = G_a[c]

    // step 2: G_a[c] *= W_1024^{a*c}; squaring ladder (depth ~5)
    {
        float sb, cb;
        __sincosf(-(float)lane * (PI_F / 512.0f), &sb, &cb);
        float2 p1 = make_float2(cb, sb);
        float2 p2 = csq(p1), p3 = cmul(p1, p2), p4 = csq(p2);
        float2 p5 = cmul(p4, p1), p6 = csq(p3), p7 = cmul(p4, p3);
        float2 w8 = csq(p4), w16 = csq(w8), w24 = cmul(w16, w8);
        g[br5(8)]  = cmul(g[br5(8)],  w8);
        g[br5(16)] = cmul(g[br5(16)], w16);
        g[br5(24)] = cmul(g[br5(24)], w24);
        float2 pc[7] = {p1, p2, p3, p4, p5, p6, p7};
#pragma unroll
        for (int c = 1; c < 8; c++) {
            float2 w = pc[c - 1];
            g[br5(c)]      = cmul(g[br5(c)], w);
            g[br5(c + 8)]  = cmul(g[br5(c + 8)],  cmul(w, w8));
            g[br5(c + 16)] = cmul(g[br5(c + 16)], cmul(w, w16));
            g[br5(c + 24)] = cmul(g[br5(c + 24)], cmul(w, w24));
        }
    }

    // step 3: 32x32 transpose through padded smem
    float2* sh = &xch[warp][0];
#pragma unroll
    for (int c = 0; c < 32; c++) sh[lane * PITCH + c] = g[br5(c)];
    __syncwarp();
#pragma unroll
    for (int a = 0; a < 32; a++) g[a] = sh[a * PITCH + lane];

    // step 4: FFT-32 over a.  g[br5(d)] = Z[lane + 32*d]
    fft32(g);
    const float re1024 = g[0].x - g[0].y;      // lane 0: ReX[1024]

    // publish Z linearly for conjugate-partner reads (conflict-free)
    __syncwarp();
#pragma unroll
    for (int d = 0; d < 32; d++) sh[lane + 32 * d] = g[br5(d)];
    __syncwarp();

    // unpack ReX[k] + LN partials; one depth-8 chain drives 4 groups
    float s = 0.f, ss = 0.f;
    {
        float su, cu;
        __sincosf(-(float)lane * (PI_F / 1024.0f), &su, &cu);
        float2 wu = make_float2(cu, su);                        // e^{-i pi k/1024}, k=lane
        const float2 ustep = make_float2(0.99518472667f, -0.09801714033f); // e^{-i pi/32}
        const float2 c8  = make_float2(RS2, -RS2);              // e^{-i pi/4}
        const float2 c24 = make_float2(-RS2, -RS2);             // e^{-i 3pi/4}
#pragma unroll
        for (int dd = 0; dd < 8; dd++) {
#pragma unroll
            for (int q = 0; q < 4; q++) {
                const int d = q * 8 + dd;
                float2 w;
                if (q == 0)      w = wu;
                else if (q == 1) w = cmul(wu, c8);
                else if (q == 2) w = make_float2(wu.y, -wu.x);  // wu * (-i)
                else             w = cmul(wu, c24);
                int k = lane + 32 * d;
                float2 z = g[br5(d)];
                float2 p = sh[(H - k) & (H - 1)];
                float red = 0.5f * ((z.x + p.x) +
                            fmaf(w.x, z.y + p.y, w.y * (z.x - p.x)));
                g[br5(d)].x = red;
                s  += 2.0f * red;
                ss = fmaf(2.0f * red, red, ss);
            }
            if (dd < 7) wu = cmul(wu, ustep);
        }
    }
    if (lane == 0) {
        float re0 = g[br5(0)].x;
        s  += re1024 - re0;
        ss += fmaf(re1024, re1024, -re0 * re0);
    }
#pragma unroll
    for (int o = 16; o > 0; o >>= 1) {
        s  += __shfl_xor_sync(0xFFFFFFFFu, s, o);
        ss += __shfl_xor_sync(0xFFFFFFFFu, ss, o);
    }
    const float mu = s * (1.0f / C);
    const float rstd = rsqrtf(ss * (1.0f / C) - mu * mu + 1e-5f);

    // stage re -> smem (reuse publish buffer; all partner reads done):
    // direct srl[k], mirror srl[2048-k]; both conflict-free (consecutive lanes)
    float* srl = reinterpret_cast<float*>(sh);
    __syncwarp();
#pragma unroll
    for (int d = 0; d < 32; d++) {
        int k = lane + 32 * d;
        float red = g[br5(d)].x;
        srl[k] = red;
        if (k != 0) srl[C - k] = red;
    }
    if (lane == 0) srl[H] = re1024;
    __syncwarp();

    // vectorized epilogue: 16 float4 per thread, fully coalesced
    const float4* s4 = reinterpret_cast<const float4*>(srl);
    const float4* g4p = reinterpret_cast<const float4*>(gamma);
    const float4* b4p = reinterpret_cast<const float4*>(beta);
    float4* o4 = reinterpret_cast<float4*>(out + row * C);
#pragma unroll
    for (int q = 0; q < 16; q++) {
        int i4 = lane + 32 * q;
        float4 sv = s4[i4];
        float4 gv = __ldg(&g4p[i4]);
        float4 bv = __ldg(&b4p[i4]);
        float4 ov;
        ov.x = fmaf((sv.x - mu) * rstd, gv.x, bv.x);
        ov.y = fmaf((sv.y - mu) * rstd, gv.y, bv.y);
        ov.z = fmaf((sv.z - mu) * rstd, gv.z, bv.z);
        ov.w = fmaf((sv.w - mu) * rstd, gv.w, bv.w);
        o4[i4] = ov;
    }
}

extern "C" void kernel_launch(void* const* d_in, const int* in_sizes, int n_in,
                              void* d_out, int out_size) {
    const float* x     = (const float*)d_in[0];
    const float* gamma = (const float*)d_in[1];
    const float* beta  = (const float*)d_in[2];
    float* out = (float*)d_out;
    int rows = in_sizes[0] / C;            // 16384
    fourier_ln_kernel<<<rows / RPC, 32 * RPC>>>(x, gamma, beta, out);
}